// round 2
// baseline (speedup 1.0000x reference)
#include <cuda_runtime.h>

#define B_ROWS 8192
#define C_COLS 2048
#define GAMA   0.3f
#define JC     1024   // j-chunk per block in pair kernel

// Scratch (device globals — no allocation allowed)
__device__ float  g_t[B_ROWS];    // valid ? pos - GAMA : +3e30 sentinel
__device__ float  g_neg[B_ROWS];  // sigmoid(masked row max)
__device__ double g_acc;
__device__ int    g_count;
__device__ int    g_y64;          // 1 if label buffer is int64, 0 if int32

__device__ __forceinline__ float sigmoidf(float v) {
    return 1.0f / (1.0f + __expf(-v));
}

// Zero accumulators (graph replays must be deterministic) and detect the label
// dtype. Reading 4096 int64 = 32 KB, within the buffer either way (int32 case
// is 8192*4 = 32 KB). int32 labels reinterpreted as int64 carry a random label
// in the high 32 bits, so "all 4096 values in [0, C)" holds only for genuine
// int64 data.
__global__ void detect_init_kernel(const long long* __restrict__ y64) {
    __shared__ int bad;
    if (threadIdx.x == 0) { bad = 0; g_acc = 0.0; g_count = 0; }
    __syncthreads();
    int local_bad = 0;
    for (int k = threadIdx.x; k < B_ROWS / 2; k += blockDim.x) {
        long long v = y64[k];
        if (v < 0 || v >= (long long)C_COLS) local_bad = 1;
    }
    if (local_bad) atomicOr(&bad, 1);
    __syncthreads();
    if (threadIdx.x == 0) g_y64 = bad ? 0 : 1;
}

// One block per row: masked max over 2048 floats (exclude col y_i and col 0),
// then sigmoid once. Monotonicity of sigmoid + sigmoid(x) > 0 for all x make
// this exactly equivalent to max over sigmoid(x) with masked entries filled
// with 0 as in the reference.
__global__ void __launch_bounds__(256) row_kernel(
    const float* __restrict__ x, const void* __restrict__ yraw) {
    int row = blockIdx.x;
    const float* xr = x + (size_t)row * C_COLS;

    int yi;
    if (g_y64) yi = (int)((const long long*)yraw)[row];
    else       yi = ((const int*)yraw)[row];

    const float4* xr4 = (const float4*)xr;
    float m = -1e30f;
    #pragma unroll
    for (int v = 0; v < 2; v++) {
        int idx4 = threadIdx.x * 2 + v;
        float4 f = xr4[idx4];
        int base = idx4 * 4;
        float a0 = (base + 0 == yi || base == 0) ? -1e30f : f.x;
        float a1 = (base + 1 == yi) ? -1e30f : f.y;
        float a2 = (base + 2 == yi) ? -1e30f : f.z;
        float a3 = (base + 3 == yi) ? -1e30f : f.w;
        m = fmaxf(m, fmaxf(fmaxf(a0, a1), fmaxf(a2, a3)));
    }
    #pragma unroll
    for (int o = 16; o; o >>= 1)
        m = fmaxf(m, __shfl_xor_sync(0xffffffffu, m, o));

    __shared__ float wmax[8];
    if ((threadIdx.x & 31) == 0) wmax[threadIdx.x >> 5] = m;
    __syncthreads();
    if (threadIdx.x == 0) {
        float mm = wmax[0];
        #pragma unroll
        for (int w = 1; w < 8; w++) mm = fmaxf(mm, wmax[w]);
        g_neg[row] = sigmoidf(mm);
        float pos = sigmoidf(xr[yi]);
        bool valid = (yi != 0);
        g_t[row] = valid ? (pos - GAMA) : 3.0e30f;  // sentinel: margin always >= 0
        if (valid) atomicAdd(&g_count, 1);
    }
}

// Pairwise: each thread owns one i, iterates a JC-sized j-chunk of neg from
// SMEM (warp-uniform address -> broadcast, conflict-free). Branchless keep via
// fminf(d, 0): invalid rows (t = +3e30) and non-kept pairs contribute exactly
// 0. 4 accumulators break the FFMA RAW chain (lat 4, rt 2).
__global__ void __launch_bounds__(256) pair_kernel() {
    __shared__ float sneg[JC];
    int jbase = blockIdx.y * JC;
    for (int j = threadIdx.x; j < JC; j += blockDim.x)
        sneg[j] = g_neg[jbase + j];
    __syncthreads();

    int i = blockIdx.x * blockDim.x + threadIdx.x;
    float t = g_t[i];
    float a0 = 0.f, a1 = 0.f, a2 = 0.f, a3 = 0.f;
    const float4* s4 = (const float4*)sneg;
    #pragma unroll 8
    for (int j = 0; j < JC / 4; j++) {
        float4 n = s4[j];
        float d0 = fminf(t - n.x, 0.f);
        float d1 = fminf(t - n.y, 0.f);
        float d2 = fminf(t - n.z, 0.f);
        float d3 = fminf(t - n.w, 0.f);
        a0 = fmaf(d0, d0, a0);
        a1 = fmaf(d1, d1, a1);
        a2 = fmaf(d2, d2, a2);
        a3 = fmaf(d3, d3, a3);
    }
    float acc = (a0 + a1) + (a2 + a3);
    #pragma unroll
    for (int o = 16; o; o >>= 1)
        acc += __shfl_xor_sync(0xffffffffu, acc, o);

    __shared__ double wsum[8];
    if ((threadIdx.x & 31) == 0) wsum[threadIdx.x >> 5] = (double)acc;
    __syncthreads();
    if (threadIdx.x == 0) {
        double s = ((wsum[0] + wsum[1]) + (wsum[2] + wsum[3]))
                 + ((wsum[4] + wsum[5]) + (wsum[6] + wsum[7]));
        atomicAdd(&g_acc, s);
    }
}

__global__ void final_kernel(float* __restrict__ out) {
    out[0] = (float)(g_acc / ((double)g_count + 1.0) / ((double)B_ROWS + 1.0));
}

extern "C" void kernel_launch(void* const* d_in, const int* in_sizes, int n_in,
                              void* d_out, int out_size) {
    const float* x = (const float*)d_in[0];
    const void*  y = d_in[1];

    detect_init_kernel<<<1, 128>>>((const long long*)y);
    row_kernel<<<B_ROWS, 256>>>(x, y);
    dim3 grid(B_ROWS / 256, B_ROWS / JC);  // (32, 8)
    pair_kernel<<<grid, 256>>>();
    final_kernel<<<1, 1>>>((float*)d_out);
}